// round 7
// baseline (speedup 1.0000x reference)
#include <cuda_runtime.h>
#include <cuda_bf16.h>
#include <math.h>

// Problem constants: B=64, L=500, F=256, H=4, dk=64
// rows (B*L) = 32000 ; bh-rows (B*H*L) = 128000

// -------------------- device scratch (no allocations allowed) --------------------
__device__ float g_wcomb[256 * 256];                    // folded W_qs @ blockdiag(W1)
__device__ float g_weight[64 * 4 * 500 * 64];           // relu(q@Wcomb+b1), [(b*4+h)*500+l][64]
__device__ float g_vh[64 * 4 * 500 * 64];               // v@W_vs,           [(b*4+h)*500+l][64]
__device__ float g_S[128000ull * 500];                  // logits -> probs (in place)
__device__ float g_attn[32000ull * 256];                // attn@vh, [b*500+l][h*64+d]
__device__ float g_tmp[32000ull * 256];                 // pre-LayerNorm

// -------------------- kernel 0: W_comb[kin][h*64+d] = sum_e W_qs[kin][h*64+e] * W1[e][d] ----------
__global__ void wcomb_kernel(const float* __restrict__ w_qs,
                             const float* __restrict__ w1,
                             float* __restrict__ out) {
    int kin = blockIdx.x;
    int c   = threadIdx.x;
    int h = c >> 6, d = c & 63;
    const float* wq = w_qs + kin * 256 + (h << 6);
    float acc = 0.f;
#pragma unroll 8
    for (int e = 0; e < 64; e++)
        acc = fmaf(wq[e], w1[(e << 6) + d], acc);
    out[kin * 256 + c] = acc;
}

// ==================== FFMA2-based SGEMM ====================
// Block tile BM x BN, 256 threads, 8x8 microtile per thread, BK=16.
// Accumulators are packed f32x2 pairs along M (A pairs come free from float4
// smem loads); B scalars broadcast-packed via mov.b64 {r,r}; inner product
// issued as fma.rn.f32x2 (FFMA2) -> 128 FMA/cyc/SM peak instead of 64.
//
// MODE 0: weight = relu(acc + b1[d]); store [(b*4+h)*500+l][d]
// MODE 1: vh     = acc;               store [(b*4+h)*500+l][d]
// MODE 2: S      = acc + b2[c];       store row*500 + c
// MODE 3: batched (z = b*4+h): attn = acc; store [(b*500+l)*256 + h*64 + d]
// MODE 4: tmp    = acc + resid[row*256+c]

__device__ __forceinline__ unsigned long long pack2(float x) {
    unsigned long long r;
    unsigned int u = __float_as_uint(x);
    asm("mov.b64 %0, {%1, %1};" : "=l"(r) : "r"(u));
    return r;
}
__device__ __forceinline__ void unpack2(unsigned long long p, float& lo, float& hi) {
    unsigned int a, b;
    asm("mov.b64 {%0, %1}, %2;" : "=r"(a), "=r"(b) : "l"(p));
    lo = __uint_as_float(a); hi = __uint_as_float(b);
}
__device__ __forceinline__ void ffma2(unsigned long long& acc,
                                      unsigned long long a, unsigned long long b) {
    asm("fma.rn.f32x2 %0, %1, %2, %3;" : "=l"(acc) : "l"(a), "l"(b), "l"(acc));
}

template <int BM, int BN, int TX, int TY, int MODE>
__global__ __launch_bounds__(256, 2) void sgemm2(
    const float* __restrict__ A, const float* __restrict__ B,
    float* __restrict__ C, int M, int N, int K, int lda, int ldb,
    const float* __restrict__ bias, const float* __restrict__ resid)
{
    static_assert(TX * TY == 256 && TX * 8 == BN && TY * 8 == BM, "shape");
    if (MODE == 3) {
        int batch = blockIdx.z;
        A += (size_t)batch * 500 * 500;
        B += (size_t)batch * 500 * 64;
    }
    __shared__ float As[16][BM + 4];   // transposed: As[k][m]
    __shared__ float Bs[16][BN + 4];   // Bs[k][n]

    const int tid = threadIdx.x;
    const int tx = tid % TX, ty = tid / TX;
    const int r0 = blockIdx.x * BM, c0 = blockIdx.y * BN;

    unsigned long long acc[4][8];      // [m-pair][n]
#pragma unroll
    for (int i = 0; i < 4; i++)
#pragma unroll
        for (int j = 0; j < 8; j++) acc[i][j] = 0ull;

    constexpr int A_F4 = (BM * 16) / (4 * 256);   // float4 loads per thread (A)
    constexpr int B_F4 = (BN * 16) / (4 * 256);   // float4 loads per thread (B)

    for (int kt = 0; kt < K; kt += 16) {
        // ---- A tile -> transposed smem ----
#pragma unroll
        for (int n = 0; n < A_F4; n++) {
            int idx = tid + n * 256;
            int row = idx >> 2;              // 4 float4 per row (BK=16)
            int kq  = (idx & 3) << 2;
            float4 av = make_float4(0.f, 0.f, 0.f, 0.f);
            int gr = r0 + row, gk = kt + kq;
            if (gr < M) {
                const float* ap = A + (size_t)gr * lda + gk;
                if (gk + 3 < K) {
                    av = *(const float4*)ap;
                } else {
                    if (gk     < K) av.x = ap[0];
                    if (gk + 1 < K) av.y = ap[1];
                    if (gk + 2 < K) av.z = ap[2];
                    if (gk + 3 < K) av.w = ap[3];
                }
            }
            As[kq + 0][row] = av.x;
            As[kq + 1][row] = av.y;
            As[kq + 2][row] = av.z;
            As[kq + 3][row] = av.w;
        }
        // ---- B tile ----
#pragma unroll
        for (int n = 0; n < B_F4; n++) {
            int idx = tid + n * 256;
            int k   = idx / (BN / 4);
            int col = (idx % (BN / 4)) << 2;
            float4 bv = make_float4(0.f, 0.f, 0.f, 0.f);
            int gk = kt + k, gc = c0 + col;
            if (gk < K) {
                const float* bp = B + (size_t)gk * ldb;
                if (gc + 3 < N) {
                    bv = *(const float4*)(bp + gc);
                } else {
                    if (gc     < N) bv.x = bp[gc];
                    if (gc + 1 < N) bv.y = bp[gc + 1];
                    if (gc + 2 < N) bv.z = bp[gc + 2];
                }
            }
            *(float4*)&Bs[k][col] = bv;
        }
        __syncthreads();

#pragma unroll
        for (int k = 0; k < 16; k++) {
            float4 a0 = *(const float4*)&As[k][ty * 8];
            float4 a1 = *(const float4*)&As[k][ty * 8 + 4];
            float4 b0 = *(const float4*)&Bs[k][tx * 8];
            float4 b1 = *(const float4*)&Bs[k][tx * 8 + 4];
            // A pairs (adjacent m) are free reinterprets of the float4s
            unsigned long long ap[4];
            ap[0] = ((const unsigned long long*)&a0)[0];
            ap[1] = ((const unsigned long long*)&a0)[1];
            ap[2] = ((const unsigned long long*)&a1)[0];
            ap[3] = ((const unsigned long long*)&a1)[1];
            // B broadcasts
            unsigned long long bb[8];
            bb[0] = pack2(b0.x); bb[1] = pack2(b0.y);
            bb[2] = pack2(b0.z); bb[3] = pack2(b0.w);
            bb[4] = pack2(b1.x); bb[5] = pack2(b1.y);
            bb[6] = pack2(b1.z); bb[7] = pack2(b1.w);
#pragma unroll
            for (int i = 0; i < 4; i++)
#pragma unroll
                for (int j = 0; j < 8; j++)
                    ffma2(acc[i][j], ap[i], bb[j]);
        }
        __syncthreads();
    }

    // ---- unpack ----
    float cf[8][8];
#pragma unroll
    for (int i = 0; i < 4; i++)
#pragma unroll
        for (int j = 0; j < 8; j++)
            unpack2(acc[i][j], cf[2 * i][j], cf[2 * i + 1][j]);

    // ---- epilogue ----
#pragma unroll
    for (int i = 0; i < 8; i++) {
        int r = r0 + ty * 8 + i;
        if (r >= M) continue;
#pragma unroll
        for (int j = 0; j < 8; j++) {
            int c = c0 + tx * 8 + j;
            if (c >= N) continue;
            float v = cf[i][j];
            if (MODE == 0) {
                int bi = r / 500, l = r % 500;
                int h = c >> 6, d = c & 63;
                v = fmaxf(v + bias[d], 0.f);
                C[(((size_t)(bi * 4 + h) * 500 + l) << 6) + d] = v;
            } else if (MODE == 1) {
                int bi = r / 500, l = r % 500;
                int h = c >> 6, d = c & 63;
                C[(((size_t)(bi * 4 + h) * 500 + l) << 6) + d] = v;
            } else if (MODE == 2) {
                C[(size_t)r * 500 + c] = v + bias[c];
            } else if (MODE == 3) {
                int batch = blockIdx.z;
                int bi = batch >> 2, h = batch & 3;
                C[((size_t)(bi * 500 + r) << 8) + (h << 6) + c] = v;
            } else { // MODE 4
                C[(size_t)r * 256 + c] = v + resid[(size_t)r * 256 + c];
            }
        }
    }
}

// -------------------- softmax over rows of length 500, in place --------------------
__global__ __launch_bounds__(128) void softmax_kernel(float* __restrict__ S) {
    float* p = S + (size_t)blockIdx.x * 500;
    const int t = threadIdx.x;
    float v[4];
    float mx = -3.4e38f;
#pragma unroll
    for (int i = 0; i < 4; i++) {
        int j = t + (i << 7);
        v[i] = (j < 500) ? p[j] : -3.4e38f;
        mx = fmaxf(mx, v[i]);
    }
#pragma unroll
    for (int o = 16; o > 0; o >>= 1)
        mx = fmaxf(mx, __shfl_xor_sync(0xffffffffu, mx, o));
    __shared__ float red[4];
    if ((t & 31) == 0) red[t >> 5] = mx;
    __syncthreads();
    mx = fmaxf(fmaxf(red[0], red[1]), fmaxf(red[2], red[3]));

    float s = 0.f;
#pragma unroll
    for (int i = 0; i < 4; i++) {
        v[i] = __expf(v[i] - mx);
        s += v[i];
    }
#pragma unroll
    for (int o = 16; o > 0; o >>= 1)
        s += __shfl_xor_sync(0xffffffffu, s, o);
    __syncthreads();
    if ((t & 31) == 0) red[t >> 5] = s;
    __syncthreads();
    float tot = red[0] + red[1] + red[2] + red[3];
    float inv = 1.0f / tot;
#pragma unroll
    for (int i = 0; i < 4; i++) {
        int j = t + (i << 7);
        if (j < 500) p[j] = v[i] * inv;
    }
}

// -------------------- LayerNorm over F=256 --------------------
__global__ __launch_bounds__(256) void ln_kernel(const float* __restrict__ X,
                                                 const float* __restrict__ gw,
                                                 const float* __restrict__ bw,
                                                 float* __restrict__ out) {
    size_t base = (size_t)blockIdx.x << 8;
    const int t = threadIdx.x;
    float x = X[base + t];
    float s = x, s2 = x * x;
#pragma unroll
    for (int o = 16; o > 0; o >>= 1) {
        s  += __shfl_xor_sync(0xffffffffu, s,  o);
        s2 += __shfl_xor_sync(0xffffffffu, s2, o);
    }
    __shared__ float rs[8], rs2[8];
    if ((t & 31) == 0) { rs[t >> 5] = s; rs2[t >> 5] = s2; }
    __syncthreads();
    s = 0.f; s2 = 0.f;
#pragma unroll
    for (int w = 0; w < 8; w++) { s += rs[w]; s2 += rs2[w]; }
    float mean = s * (1.f / 256.f);
    float var  = s2 * (1.f / 256.f) - mean * mean;
    float r = rsqrtf(var + 1e-6f);
    out[base + t] = (x - mean) * r * gw[t] + bw[t];
}

// -------------------- launch --------------------
extern "C" void kernel_launch(void* const* d_in, const int* in_sizes, int n_in,
                              void* d_out, int out_size) {
    const float* q    = (const float*)d_in[0];
    // d_in[1] = k : unused by the reference computation
    const float* v    = (const float*)d_in[2];
    const float* w_qs = (const float*)d_in[3];
    const float* w_vs = (const float*)d_in[4];
    const float* w1   = (const float*)d_in[5];
    const float* b1   = (const float*)d_in[6];
    const float* w2   = (const float*)d_in[7];
    const float* b2   = (const float*)d_in[8];
    const float* fc_w = (const float*)d_in[9];
    const float* ln_g = (const float*)d_in[10];
    const float* ln_b = (const float*)d_in[11];
    float* out = (float*)d_out;

    float *wcomb, *weight, *vh, *S, *attn, *tmp;
    cudaGetSymbolAddress((void**)&wcomb,  g_wcomb);
    cudaGetSymbolAddress((void**)&weight, g_weight);
    cudaGetSymbolAddress((void**)&vh,     g_vh);
    cudaGetSymbolAddress((void**)&S,      g_S);
    cudaGetSymbolAddress((void**)&attn,   g_attn);
    cudaGetSymbolAddress((void**)&tmp,    g_tmp);

    // 0) fold W_qs @ blockdiag(W1) -> Wcomb
    wcomb_kernel<<<256, 256>>>(w_qs, w1, wcomb);

    // 1) weight = relu(q @ Wcomb + b1)
    sgemm2<128, 128, 16, 16, 0><<<dim3(250, 2, 1), 256>>>(
        q, wcomb, weight, 32000, 256, 256, 256, 256, b1, nullptr);

    // 2) vh = v @ W_vs
    sgemm2<128, 128, 16, 16, 1><<<dim3(250, 2, 1), 256>>>(
        v, w_vs, vh, 32000, 256, 256, 256, 256, nullptr, nullptr);

    // 3) S = weight @ W2 + b2   (M=128000, N=500, K=64)
    sgemm2<128, 128, 16, 16, 2><<<dim3(1000, 4, 1), 256>>>(
        weight, w2, S, 128000, 500, 64, 64, 500, b2, nullptr);

    // 4) softmax rows of S in place
    softmax_kernel<<<128000, 128>>>(S);

    // 5) attn = P @ vh, batched over 256 (b,h)
    sgemm2<256, 64, 8, 32, 3><<<dim3(2, 1, 256), 256>>>(
        S, vh, attn, 500, 64, 500, 500, 64, nullptr, nullptr);

    // 6) tmp = attn @ fc_w + q
    sgemm2<128, 128, 16, 16, 4><<<dim3(250, 2, 1), 256>>>(
        attn, fc_w, tmp, 32000, 256, 256, 256, 256, nullptr, q);

    // 7) LayerNorm -> output
    ln_kernel<<<32000, 256>>>(tmp, ln_g, ln_b, out);
}